// round 9
// baseline (speedup 1.0000x reference)
#include <cuda_runtime.h>

#define NN    30000
#define NE    600000
#define C_IN  256
#define C_HID 128
#define C_OUT 64

// ---------------- scratch (device globals — no allocation allowed) ----------
__device__ int   g_deg[NN];
__device__ float g_dinv[NN];
__device__ int   g_rowptr[NN + 1];
__device__ int   g_cursor[NN];
__device__ int   g_col[NE];
__device__ int   g_is64;
__device__ float g_hs1[(size_t)NN * C_HID];   // dinv * (X @ W1)
__device__ float g_h2 [(size_t)NN * C_HID];   // relu(agg1 + b1)
__device__ float g_hs2[(size_t)NN * C_OUT];   // dinv * (h2 @ W2)

// ---------------- packed fp32x2 helpers (sm_100+) ---------------------------
__device__ __forceinline__ unsigned long long ffma2(unsigned long long a,
                                                    unsigned long long b,
                                                    unsigned long long c) {
    unsigned long long d;
    asm("fma.rn.f32x2 %0, %1, %2, %3;" : "=l"(d) : "l"(a), "l"(b), "l"(c));
    return d;
}
__device__ __forceinline__ void unpack2(unsigned long long v, float& lo, float& hi) {
    unsigned l, h;
    asm("mov.b64 {%0,%1}, %2;" : "=r"(l), "=r"(h) : "l"(v));
    lo = __uint_as_float(l); hi = __uint_as_float(h);
}

// ---------------- edge dtype detection (int64 vs int32) ---------------------
__global__ void detect_kernel(const long long* __restrict__ p) {
    if (blockIdx.x == 0 && threadIdx.x == 0) {
        int ok = 1;
        for (int e = 0; e < 64; e++) {
            long long v = p[e];
            if (v < 0 || v >= NN) { ok = 0; break; }
        }
        g_is64 = ok;
    }
}

// ---------------- CSR build --------------------------------------------------
__global__ void zero_deg_kernel() {
    int i = blockIdx.x * blockDim.x + threadIdx.x;
    if (i < NN) g_deg[i] = 0;
}

__global__ void count_deg_kernel(const void* __restrict__ ei) {
    int e = blockIdx.x * blockDim.x + threadIdx.x;
    if (e >= NE) return;
    int d;
    if (g_is64) d = (int)((const long long*)ei)[NE + e];
    else        d = ((const int*)ei)[NE + e];
    atomicAdd(&g_deg[d], 1);
}

__global__ void dinv_kernel() {
    int i = blockIdx.x * blockDim.x + threadIdx.x;
    if (i < NN) g_dinv[i] = rsqrtf((float)(g_deg[i] + 1));  // +1 self loop
}

// single-block chunked exclusive scan, shuffle-based (2 bars per 1024-chunk)
__global__ void scan_kernel() {
    __shared__ int warp_sums[32];
    int tid = threadIdx.x, lane = tid & 31, wid = tid >> 5;
    int carry = 0;
    for (int base = 0; base < NN; base += 1024) {
        int i = base + tid;
        int v = (i < NN) ? g_deg[i] : 0;
        int s = v;                                  // inclusive warp scan
        #pragma unroll
        for (int o = 1; o < 32; o <<= 1) {
            int t = __shfl_up_sync(0xffffffffu, s, o);
            if (lane >= o) s += t;
        }
        if (lane == 31) warp_sums[wid] = s;
        __syncthreads();
        if (wid == 0) {
            int ws = warp_sums[lane];
            #pragma unroll
            for (int o = 1; o < 32; o <<= 1) {
                int t = __shfl_up_sync(0xffffffffu, ws, o);
                if (lane >= o) ws += t;
            }
            warp_sums[lane] = ws;
        }
        __syncthreads();
        int warp_excl = (wid == 0) ? 0 : warp_sums[wid - 1];
        int excl = carry + warp_excl + s - v;
        if (i < NN) { g_rowptr[i] = excl; g_cursor[i] = excl; }
        carry += warp_sums[31];
        __syncthreads();                            // protect warp_sums reuse
    }
    if (tid == 0) g_rowptr[NN] = carry;
}

__global__ void scatter_kernel(const void* __restrict__ ei) {
    int e = blockIdx.x * blockDim.x + threadIdx.x;
    if (e >= NE) return;
    int s, d;
    if (g_is64) {
        s = (int)((const long long*)ei)[e];
        d = (int)((const long long*)ei)[NE + e];
    } else {
        s = ((const int*)ei)[e];
        d = ((const int*)ei)[NE + e];
    }
    int pos = atomicAdd(&g_cursor[d], 1);
    g_col[pos] = s;
}

// ---------------- GEMM with fused dinv row-scale, packed f32x2 FMA ----------
// C[row, n] = dinv[row] * sum_k X[row,k] * W[k,n]
// Accumulators packed along M (pairs of adjacent rows). A slab stored
// transposed so M-pairs load as contiguous 64-bit lanes; B slab stored
// duplicated ({b,b} pairs) so broadcasts need no per-iteration packing.
template<int BM, int BN, int BK, int K, int LAYER>
__global__ __launch_bounds__(256)
void gemm_dinv_kernel(const float* __restrict__ Xin, const float* __restrict__ W) {
    static_assert(BM * BN == 256 * 32, "tile/thread mismatch");
    constexpr int TM = 8, TN = 4;
    constexpr int TX = BN / TN;            // threads along n
    constexpr int AQ = BK / 4;             // float4 chunks per A row
    constexpr int LA = BM * AQ / 256;      // A float4 loads per thread
    constexpr int BQ = BN / 4;
    constexpr int LB = BK * BQ / 256;      // B(gmem) float4 loads per thread

    const float* X;
    float*       out;
    if constexpr (LAYER == 1) { X = Xin;                out = g_hs1; }
    else                      { X = (const float*)g_h2; out = g_hs2; }

    __shared__ float As[BK][BM + 4];       // transposed A slab
    __shared__ float Bs[BK][2 * BN];       // duplicated B slab: [2n]=[2n+1]=W[k][n]

    const int tid  = threadIdx.x;
    const int tx   = tid % TX;
    const int ty   = tid / TX;
    const int bRow = blockIdx.x * BM;

    unsigned long long acc[TM / 2][TN];    // pair j covers rows (2j, 2j+1)
    #pragma unroll
    for (int j = 0; j < TM / 2; j++)
        #pragma unroll
        for (int n = 0; n < TN; n++) acc[j][n] = 0ull;  // {0.f, 0.f}

    for (int k0 = 0; k0 < K; k0 += BK) {
        #pragma unroll
        for (int l = 0; l < LA; l++) {
            int li = tid + l * 256;
            int r  = li / AQ, cq = li % AQ;
            int grow = bRow + r;
            float4 v = make_float4(0.f, 0.f, 0.f, 0.f);
            if (grow < NN)
                v = *(const float4*)&X[(size_t)grow * K + k0 + cq * 4];
            As[cq * 4 + 0][r] = v.x;
            As[cq * 4 + 1][r] = v.y;
            As[cq * 4 + 2][r] = v.z;
            As[cq * 4 + 3][r] = v.w;
        }
        #pragma unroll
        for (int l = 0; l < LB; l++) {
            int li = tid + l * 256;
            int r  = li / BQ, cq = li % BQ;
            float4 v = *(const float4*)&W[(size_t)(k0 + r) * BN + cq * 4];
            *(float4*)&Bs[r][cq * 8]     = make_float4(v.x, v.x, v.y, v.y);
            *(float4*)&Bs[r][cq * 8 + 4] = make_float4(v.z, v.z, v.w, v.w);
        }
        __syncthreads();

        #pragma unroll
        for (int kk = 0; kk < BK; kk++) {
            // a pairs: contiguous adjacent-m values -> direct 64-bit lanes
            ulonglong2 av0 = *(const ulonglong2*)&As[kk][ty * TM];      // {a0,a1},{a2,a3}
            ulonglong2 av1 = *(const ulonglong2*)&As[kk][ty * TM + 4];  // {a4,a5},{a6,a7}
            // b pairs: duplicated {b,b}
            ulonglong2 bv0 = *(const ulonglong2*)&Bs[kk][8 * tx];       // {b0,b0},{b1,b1}
            ulonglong2 bv1 = *(const ulonglong2*)&Bs[kk][8 * tx + 4];   // {b2,b2},{b3,b3}
            unsigned long long a[4] = {av0.x, av0.y, av1.x, av1.y};
            unsigned long long b[4] = {bv0.x, bv0.y, bv1.x, bv1.y};
            #pragma unroll
            for (int j = 0; j < 4; j++) {
                acc[j][0] = ffma2(a[j], b[0], acc[j][0]);
                acc[j][1] = ffma2(a[j], b[1], acc[j][1]);
                acc[j][2] = ffma2(a[j], b[2], acc[j][2]);
                acc[j][3] = ffma2(a[j], b[3], acc[j][3]);
            }
        }
        __syncthreads();
    }

    #pragma unroll
    for (int j = 0; j < TM / 2; j++) {
        float lo[TN], hi[TN];
        #pragma unroll
        for (int n = 0; n < TN; n++) unpack2(acc[j][n], lo[n], hi[n]);
        int r0 = bRow + ty * TM + 2 * j;
        int r1 = r0 + 1;
        if (r0 < NN) {
            float s = g_dinv[r0];
            *(float4*)&out[(size_t)r0 * BN + tx * TN] =
                make_float4(lo[0] * s, lo[1] * s, lo[2] * s, lo[3] * s);
        }
        if (r1 < NN) {
            float s = g_dinv[r1];
            *(float4*)&out[(size_t)r1 * BN + tx * TN] =
                make_float4(hi[0] * s, hi[1] * s, hi[2] * s, hi[3] * s);
        }
    }
}

// ---------------- CSR aggregation: one warp per node -------------------------
// out[i] = (relu?)( dinv[i] * (hs[i] + sum_{s in in(i)} hs[s]) + bias )
template<int C, bool RELU>
__global__ void aggregate_kernel(const float* __restrict__ bias,
                                 float* __restrict__ outParam) {
    constexpr int V = C / 32;              // floats per lane (4 or 2)
    int gw = (blockIdx.x * blockDim.x + threadIdx.x) >> 5;
    if (gw >= NN) return;
    int lane = threadIdx.x & 31;
    int off  = lane * V;

    const float* hs;
    float*       out;
    if constexpr (RELU) { hs = g_hs1; out = g_h2; }       // layer 1
    else                { hs = g_hs2; out = outParam; }   // layer 2

    float acc[V];
    {
        const float* p = hs + (size_t)gw * C + off;
        if constexpr (V == 4) {
            float4 t = *(const float4*)p;
            acc[0] = t.x; acc[1] = t.y; acc[2] = t.z; acc[3] = t.w;
        } else {
            float2 t = *(const float2*)p;
            acc[0] = t.x; acc[1] = t.y;
        }
    }

    int s = g_rowptr[gw];
    int e = g_rowptr[gw + 1];
    for (int i = s; i < e; i++) {
        int src = g_col[i];
        const float* p = hs + (size_t)src * C + off;
        if constexpr (V == 4) {
            float4 t = *(const float4*)p;
            acc[0] += t.x; acc[1] += t.y; acc[2] += t.z; acc[3] += t.w;
        } else {
            float2 t = *(const float2*)p;
            acc[0] += t.x; acc[1] += t.y;
        }
    }

    float di = g_dinv[gw];
    float r[V];
    #pragma unroll
    for (int v = 0; v < V; v++) {
        float val = fmaf(acc[v], di, bias[off + v]);
        if (RELU) val = fmaxf(val, 0.f);
        r[v] = val;
    }
    float* q = out + (size_t)gw * C + off;
    if constexpr (V == 4) *(float4*)q = make_float4(r[0], r[1], r[2], r[3]);
    else                  *(float2*)q = make_float2(r[0], r[1]);
}

// ---------------- launch ------------------------------------------------------
extern "C" void kernel_launch(void* const* d_in, const int* in_sizes, int n_in,
                              void* d_out, int out_size) {
    const float* x  = (const float*)d_in[0];
    const void*  ei = d_in[1];                 // int64 (or int32) [2, E]
    const float* W1 = (const float*)d_in[2];
    const float* b1 = (const float*)d_in[3];
    const float* W2 = (const float*)d_in[4];
    const float* b2 = (const float*)d_in[5];
    float* out = (float*)d_out;

    // CSR build
    detect_kernel<<<1, 32>>>((const long long*)ei);
    zero_deg_kernel<<<(NN + 255) / 256, 256>>>();
    count_deg_kernel<<<(NE + 255) / 256, 256>>>(ei);
    dinv_kernel<<<(NN + 255) / 256, 256>>>();
    scan_kernel<<<1, 1024>>>();
    scatter_kernel<<<(NE + 255) / 256, 256>>>(ei);

    // layer 1: hs1 = dinv * (x @ W1);  h2 = relu(dinv * (A_sum hs1) + b1)
    constexpr int G1 = (NN + 63) / 64;     // 469
    gemm_dinv_kernel<64, 128, 16, C_IN, 1><<<G1, 256>>>(x, W1);
    aggregate_kernel<C_HID, true><<<(NN * 32 + 255) / 256, 256>>>(b1, nullptr);

    // layer 2: hs2 = dinv * (h2 @ W2);  out = dinv * (A_sum hs2) + b2
    constexpr int G2 = (NN + 127) / 128;   // 235
    gemm_dinv_kernel<128, 64, 16, C_HID, 2><<<G2, 256>>>(nullptr, W2);
    aggregate_kernel<C_OUT, false><<<(NN * 32 + 255) / 256, 256>>>(b2, out);
}

// round 11
// speedup vs baseline: 1.4954x; 1.4954x over previous
#include <cuda_runtime.h>
#include <cuda_bf16.h>
#include <cstdint>

#define NN    30000
#define NE    600000
#define C_IN  256
#define C_HID 128
#define C_OUT 64

// ---------------- scratch (device globals — no allocation allowed) ----------
__device__ int   g_deg[NN];
__device__ float g_dinv[NN];
__device__ int   g_rowptr[NN + 1];
__device__ int   g_cursor[NN];
__device__ int   g_col[NE];
__device__ int   g_is64;
__device__ float g_hs1[(size_t)NN * C_HID];   // dinv * (X @ W1)
__device__ float g_hs2[(size_t)NN * C_OUT];   // dinv * (h2 @ W2)
// bf16 split operands for tensor-core GEMMs
__device__ __nv_bfloat16 g_xhi [(size_t)NN * C_IN];
__device__ __nv_bfloat16 g_xlo [(size_t)NN * C_IN];
__device__ __nv_bfloat16 g_h2hi[(size_t)NN * C_HID];
__device__ __nv_bfloat16 g_h2lo[(size_t)NN * C_HID];
__device__ __nv_bfloat16 g_w1thi[C_HID * C_IN];   // W1^T [n][k]
__device__ __nv_bfloat16 g_w1tlo[C_HID * C_IN];
__device__ __nv_bfloat16 g_w2thi[C_OUT * C_HID];  // W2^T [n][k]
__device__ __nv_bfloat16 g_w2tlo[C_OUT * C_HID];

// ---------------- edge dtype detection (int64 vs int32) ---------------------
__global__ void detect_kernel(const long long* __restrict__ p) {
    if (blockIdx.x == 0 && threadIdx.x == 0) {
        int ok = 1;
        for (int e = 0; e < 64; e++) {
            long long v = p[e];
            if (v < 0 || v >= NN) { ok = 0; break; }
        }
        g_is64 = ok;
    }
}

// ---------------- CSR build --------------------------------------------------
__global__ void zero_deg_kernel() {
    int i = blockIdx.x * blockDim.x + threadIdx.x;
    if (i < NN) g_deg[i] = 0;
}

__global__ void count_deg_kernel(const void* __restrict__ ei) {
    int e = blockIdx.x * blockDim.x + threadIdx.x;
    if (e >= NE) return;
    int d;
    if (g_is64) d = (int)((const long long*)ei)[NE + e];
    else        d = ((const int*)ei)[NE + e];
    atomicAdd(&g_deg[d], 1);
}

__global__ void dinv_kernel() {
    int i = blockIdx.x * blockDim.x + threadIdx.x;
    if (i < NN) g_dinv[i] = rsqrtf((float)(g_deg[i] + 1));  // +1 self loop
}

// single-block chunked exclusive scan, shuffle-based
__global__ void scan_kernel() {
    __shared__ int warp_sums[32];
    int tid = threadIdx.x, lane = tid & 31, wid = tid >> 5;
    int carry = 0;
    for (int base = 0; base < NN; base += 1024) {
        int i = base + tid;
        int v = (i < NN) ? g_deg[i] : 0;
        int s = v;
        #pragma unroll
        for (int o = 1; o < 32; o <<= 1) {
            int t = __shfl_up_sync(0xffffffffu, s, o);
            if (lane >= o) s += t;
        }
        if (lane == 31) warp_sums[wid] = s;
        __syncthreads();
        if (wid == 0) {
            int ws = warp_sums[lane];
            #pragma unroll
            for (int o = 1; o < 32; o <<= 1) {
                int t = __shfl_up_sync(0xffffffffu, ws, o);
                if (lane >= o) ws += t;
            }
            warp_sums[lane] = ws;
        }
        __syncthreads();
        int warp_excl = (wid == 0) ? 0 : warp_sums[wid - 1];
        int excl = carry + warp_excl + s - v;
        if (i < NN) { g_rowptr[i] = excl; g_cursor[i] = excl; }
        carry += warp_sums[31];
        __syncthreads();
    }
    if (tid == 0) g_rowptr[NN] = carry;
}

__global__ void scatter_kernel(const void* __restrict__ ei) {
    int e = blockIdx.x * blockDim.x + threadIdx.x;
    if (e >= NE) return;
    int s, d;
    if (g_is64) {
        s = (int)((const long long*)ei)[e];
        d = (int)((const long long*)ei)[NE + e];
    } else {
        s = ((const int*)ei)[e];
        d = ((const int*)ei)[NE + e];
    }
    int pos = atomicAdd(&g_cursor[d], 1);
    g_col[pos] = s;
}

// ---------------- bf16 split prep --------------------------------------------
__device__ __forceinline__ void split_bf16(float v, __nv_bfloat16& hi,
                                           __nv_bfloat16& lo) {
    hi = __float2bfloat16(v);
    lo = __float2bfloat16(v - __bfloat162float(hi));
}

__global__ void prep_x_kernel(const float* __restrict__ x) {
    int i = blockIdx.x * blockDim.x + threadIdx.x;     // float4 index
    if (i >= NN * C_IN / 4) return;
    float4 v = ((const float4*)x)[i];
    __nv_bfloat16 h[4], l[4];
    split_bf16(v.x, h[0], l[0]); split_bf16(v.y, h[1], l[1]);
    split_bf16(v.z, h[2], l[2]); split_bf16(v.w, h[3], l[3]);
    *(uint2*)&g_xhi[(size_t)i * 4] = *(uint2*)h;
    *(uint2*)&g_xlo[(size_t)i * 4] = *(uint2*)l;
}

__global__ void prep_w_kernel(const float* __restrict__ W1,
                              const float* __restrict__ W2) {
    int i = blockIdx.x * blockDim.x + threadIdx.x;
    if (i < C_HID * C_IN) {                 // W1^T[n][k] = W1[k][n]
        int n = i / C_IN, k = i % C_IN;
        split_bf16(W1[(size_t)k * C_HID + n], g_w1thi[i], g_w1tlo[i]);
    } else if (i < C_HID * C_IN + C_OUT * C_HID) {
        int j = i - C_HID * C_IN;           // W2^T[n][k] = W2[k][n]
        int n = j / C_HID, k = j % C_HID;
        split_bf16(W2[(size_t)k * C_OUT + n], g_w2thi[j], g_w2tlo[j]);
    }
}

// ---------------- mma.sync helpers (baseline PTX — no sm_103a features) -----
__device__ __forceinline__ void ldm_x4(uint32_t& r0, uint32_t& r1,
                                       uint32_t& r2, uint32_t& r3,
                                       uint32_t addr) {
    asm volatile("ldmatrix.sync.aligned.m8n8.x4.shared.b16 {%0,%1,%2,%3}, [%4];"
                 : "=r"(r0), "=r"(r1), "=r"(r2), "=r"(r3) : "r"(addr));
}
__device__ __forceinline__ void mma_bf16(float* c, const uint32_t* a,
                                         const uint32_t* b) {
    asm volatile(
        "mma.sync.aligned.m16n8k16.row.col.f32.bf16.bf16.f32 "
        "{%0,%1,%2,%3}, {%4,%5,%6,%7}, {%8,%9}, {%0,%1,%2,%3};"
        : "+f"(c[0]), "+f"(c[1]), "+f"(c[2]), "+f"(c[3])
        : "r"(a[0]), "r"(a[1]), "r"(a[2]), "r"(a[3]), "r"(b[0]), "r"(b[1]));
}
__device__ __forceinline__ uint32_t smem_u32(const void* p) {
    uint32_t a;
    asm("{ .reg .u64 t; cvta.to.shared.u64 t, %1; cvt.u32.u64 %0, t; }"
        : "=r"(a) : "l"(p));
    return a;
}

// ---------------- tensor-core GEMM (HMMA fallback) with fused dinv scale ----
// out[row, n] = dinv[row] * sum_k A[row,k] * WT[n,k]
// 3-term bf16 split: AhiBhi + AloBhi + AhiBlo, fp32 accumulate.
// BM=128, BN = full N, BK=32, 256 threads = 8 warps (4 M x 2 N).
template<int BN, int K_TOT, int LAYER>
__global__ __launch_bounds__(256)
void gemm_mma_kernel() {
    constexpr int BM = 128, BK = 32;
    constexpr int STRIDE = BK + 8;              // bf16 units; 80B rows (conflict-free)
    constexpr int WN = BN / 2;                  // warp n-extent (64 / 32)
    constexpr int NFRAG = WN / 8;               // 8 / 4
    constexpr int MFRAG = 2;                    // 32 rows per warp

    const __nv_bfloat16 *Ahi, *Alo, *Bhi, *Blo;
    float* out;
    if constexpr (LAYER == 1) {
        Ahi = g_xhi;  Alo = g_xlo;  Bhi = g_w1thi; Blo = g_w1tlo; out = g_hs1;
    } else {
        Ahi = g_h2hi; Alo = g_h2lo; Bhi = g_w2thi; Blo = g_w2tlo; out = g_hs2;
    }

    __shared__ __nv_bfloat16 sAh[BM * STRIDE], sAl[BM * STRIDE];
    __shared__ __nv_bfloat16 sBh[BN * STRIDE], sBl[BN * STRIDE];

    const int tid   = threadIdx.x;
    const int wid   = tid >> 5, lane = tid & 31;
    const int warp_m = wid & 3, warp_n = wid >> 2;
    const int bRow  = blockIdx.x * BM;

    const uint32_t uAh = smem_u32(sAh), uAl = smem_u32(sAl);
    const uint32_t uBh = smem_u32(sBh), uBl = smem_u32(sBl);

    float acc[MFRAG][NFRAG][4];
    #pragma unroll
    for (int f = 0; f < MFRAG; f++)
        #pragma unroll
        for (int n = 0; n < NFRAG; n++)
            #pragma unroll
            for (int c = 0; c < 4; c++) acc[f][n][c] = 0.f;

    // ldmatrix per-lane row/col (same pattern for A[M][K] and B[N][K])
    const int lrow = lane & 15;
    const int lcol = (lane >> 4) << 3;

    for (int k0 = 0; k0 < K_TOT; k0 += BK) {
        // A slabs: BM x BK, vectorized uint4 (8 bf16)
        #pragma unroll
        for (int t = 0; t < BM * BK / 8 / 256; t++) {
            int u = t * 256 + tid;
            int r = u >> 2, c = u & 3;                  // 4 uint4 per row
            int grow = bRow + r;
            uint4 vh = make_uint4(0, 0, 0, 0), vl = make_uint4(0, 0, 0, 0);
            if (grow < NN) {
                size_t src = (size_t)grow * K_TOT + k0 + c * 8;
                vh = *(const uint4*)&Ahi[src];
                vl = *(const uint4*)&Alo[src];
            }
            *(uint4*)&sAh[r * STRIDE + c * 8] = vh;
            *(uint4*)&sAl[r * STRIDE + c * 8] = vl;
        }
        // B slabs: BN x BK
        #pragma unroll
        for (int t = 0; t < (BN * BK / 8 + 255) / 256; t++) {
            int u = t * 256 + tid;
            if (u < BN * BK / 8) {
                int r = u >> 2, c = u & 3;
                size_t src = (size_t)r * K_TOT + k0 + c * 8;
                *(uint4*)&sBh[r * STRIDE + c * 8] = *(const uint4*)&Bhi[src];
                *(uint4*)&sBl[r * STRIDE + c * 8] = *(const uint4*)&Blo[src];
            }
        }
        __syncthreads();

        #pragma unroll
        for (int kk = 0; kk < BK; kk += 16) {
            uint32_t ah[MFRAG][4], al[MFRAG][4];
            #pragma unroll
            for (int f = 0; f < MFRAG; f++) {
                uint32_t off = (uint32_t)((warp_m * 32 + f * 16 + lrow) * STRIDE
                                          + kk + lcol) * 2;
                ldm_x4(ah[f][0], ah[f][1], ah[f][2], ah[f][3], uAh + off);
                ldm_x4(al[f][0], al[f][1], al[f][2], al[f][3], uAl + off);
            }
            uint32_t bh[NFRAG][2], bl[NFRAG][2];
            #pragma unroll
            for (int g = 0; g < NFRAG / 2; g++) {
                uint32_t off = (uint32_t)((warp_n * WN + g * 16 + lrow) * STRIDE
                                          + kk + lcol) * 2;
                uint32_t r0, r1, r2, r3;
                ldm_x4(r0, r1, r2, r3, uBh + off);
                bh[2*g][0] = r0; bh[2*g][1] = r2;
                bh[2*g+1][0] = r1; bh[2*g+1][1] = r3;
                ldm_x4(r0, r1, r2, r3, uBl + off);
                bl[2*g][0] = r0; bl[2*g][1] = r2;
                bl[2*g+1][0] = r1; bl[2*g+1][1] = r3;
            }
            #pragma unroll
            for (int f = 0; f < MFRAG; f++)
                #pragma unroll
                for (int n = 0; n < NFRAG; n++) {
                    mma_bf16(acc[f][n], ah[f], bh[n]);   // hi*hi
                    mma_bf16(acc[f][n], al[f], bh[n]);   // lo*hi
                    mma_bf16(acc[f][n], ah[f], bl[n]);   // hi*lo
                }
        }
        __syncthreads();
    }

    // epilogue: D frag -> lane holds rows (q, q+8), cols 2*(lane%4)+{0,1}
    const int q  = lane >> 2;
    const int cc = (lane & 3) * 2;
    #pragma unroll
    for (int f = 0; f < MFRAG; f++) {
        int r0 = bRow + warp_m * 32 + f * 16 + q;
        int r1 = r0 + 8;
        float s0 = (r0 < NN) ? g_dinv[r0] : 0.f;
        float s1 = (r1 < NN) ? g_dinv[r1] : 0.f;
        #pragma unroll
        for (int n = 0; n < NFRAG; n++) {
            int col = warp_n * WN + n * 8 + cc;
            if (r0 < NN)
                *(float2*)&out[(size_t)r0 * BN + col] =
                    make_float2(acc[f][n][0] * s0, acc[f][n][1] * s0);
            if (r1 < NN)
                *(float2*)&out[(size_t)r1 * BN + col] =
                    make_float2(acc[f][n][2] * s1, acc[f][n][3] * s1);
        }
    }
}

// ---------------- CSR aggregation: one warp per node -------------------------
// layer 1: h2 = relu(dinv*(hs1[i] + sum_nbr) + b1), emitted as bf16 hi/lo split
__global__ void aggregate1_kernel(const float* __restrict__ bias) {
    int gw = (blockIdx.x * blockDim.x + threadIdx.x) >> 5;
    if (gw >= NN) return;
    int lane = threadIdx.x & 31;
    int off  = lane * 4;

    float acc[4];
    {
        float4 t = *(const float4*)&g_hs1[(size_t)gw * C_HID + off];
        acc[0] = t.x; acc[1] = t.y; acc[2] = t.z; acc[3] = t.w;
    }
    int s = g_rowptr[gw], e = g_rowptr[gw + 1];
    for (int i = s; i < e; i++) {
        int src = g_col[i];
        float4 t = *(const float4*)&g_hs1[(size_t)src * C_HID + off];
        acc[0] += t.x; acc[1] += t.y; acc[2] += t.z; acc[3] += t.w;
    }
    float di = g_dinv[gw];
    __nv_bfloat16 h[4], l[4];
    #pragma unroll
    for (int v = 0; v < 4; v++) {
        float val = fmaxf(fmaf(acc[v], di, bias[off + v]), 0.f);
        split_bf16(val, h[v], l[v]);
    }
    size_t idx = (size_t)gw * C_HID + off;
    *(uint2*)&g_h2hi[idx] = *(uint2*)h;
    *(uint2*)&g_h2lo[idx] = *(uint2*)l;
}

// layer 2: out = dinv*(hs2[i] + sum_nbr) + b2   (fp32 to d_out)
__global__ void aggregate2_kernel(const float* __restrict__ bias,
                                  float* __restrict__ out) {
    int gw = (blockIdx.x * blockDim.x + threadIdx.x) >> 5;
    if (gw >= NN) return;
    int lane = threadIdx.x & 31;
    int off  = lane * 2;

    float acc[2];
    {
        float2 t = *(const float2*)&g_hs2[(size_t)gw * C_OUT + off];
        acc[0] = t.x; acc[1] = t.y;
    }
    int s = g_rowptr[gw], e = g_rowptr[gw + 1];
    for (int i = s; i < e; i++) {
        int src = g_col[i];
        float2 t = *(const float2*)&g_hs2[(size_t)src * C_OUT + off];
        acc[0] += t.x; acc[1] += t.y;
    }
    float di = g_dinv[gw];
    float2 r = make_float2(fmaf(acc[0], di, bias[off]),
                           fmaf(acc[1], di, bias[off + 1]));
    *(float2*)&out[(size_t)gw * C_OUT + off] = r;
}

// ---------------- launch ------------------------------------------------------
extern "C" void kernel_launch(void* const* d_in, const int* in_sizes, int n_in,
                              void* d_out, int out_size) {
    const float* x  = (const float*)d_in[0];
    const void*  ei = d_in[1];                 // int64 (or int32) [2, E]
    const float* W1 = (const float*)d_in[2];
    const float* b1 = (const float*)d_in[3];
    const float* W2 = (const float*)d_in[4];
    const float* b2 = (const float*)d_in[5];
    float* out = (float*)d_out;

    // CSR build
    detect_kernel<<<1, 32>>>((const long long*)ei);
    zero_deg_kernel<<<(NN + 255) / 256, 256>>>();
    count_deg_kernel<<<(NE + 255) / 256, 256>>>(ei);
    dinv_kernel<<<(NN + 255) / 256, 256>>>();
    scan_kernel<<<1, 1024>>>();
    scatter_kernel<<<(NE + 255) / 256, 256>>>(ei);

    // operand prep (bf16 splits)
    prep_w_kernel<<<(C_HID * C_IN + C_OUT * C_HID + 255) / 256, 256>>>(W1, W2);
    prep_x_kernel<<<(NN * C_IN / 4 + 255) / 256, 256>>>(x);

    constexpr int GB = (NN + 127) / 128;  // 235 CTAs
    // layer 1
    gemm_mma_kernel<C_HID, C_IN, 1><<<GB, 256>>>();
    aggregate1_kernel<<<(NN * 32 + 255) / 256, 256>>>(b1);
    // layer 2
    gemm_mma_kernel<C_OUT, C_HID, 2><<<GB, 256>>>();
    aggregate2_kernel<<<(NN * 32 + 255) / 256, 256>>>(b2, out);
}

// round 12
// speedup vs baseline: 1.5177x; 1.0149x over previous
#include <cuda_runtime.h>
#include <cuda_bf16.h>
#include <cstdint>

#define NN    30000
#define NE    600000
#define C_IN  256
#define C_HID 128
#define C_OUT 64

// ---------------- scratch (device globals — no allocation allowed) ----------
__device__ int   g_deg[NN];
__device__ float g_dinv[NN];
__device__ int   g_rowptr[NN + 1];
__device__ int   g_cursor[NN];
__device__ int   g_col[NE];
__device__ int   g_is64;
__device__ float g_hs1[(size_t)NN * C_HID];   // dinv * (X @ W1)
__device__ float g_hs2[(size_t)NN * C_OUT];   // dinv * (h2 @ W2)
// bf16 split operands for tensor-core GEMMs
__device__ __nv_bfloat16 g_xhi [(size_t)NN * C_IN];
__device__ __nv_bfloat16 g_xlo [(size_t)NN * C_IN];
__device__ __nv_bfloat16 g_h2hi[(size_t)NN * C_HID];
__device__ __nv_bfloat16 g_h2lo[(size_t)NN * C_HID];
__device__ __nv_bfloat16 g_w1thi[C_HID * C_IN];   // W1^T [n][k]
__device__ __nv_bfloat16 g_w1tlo[C_HID * C_IN];
__device__ __nv_bfloat16 g_w2thi[C_OUT * C_HID];  // W2^T [n][k]
__device__ __nv_bfloat16 g_w2tlo[C_OUT * C_HID];

// ---------------- init: zero degrees + edge dtype detection (fused) ---------
__global__ void init_kernel(const long long* __restrict__ p) {
    int i = blockIdx.x * blockDim.x + threadIdx.x;
    if (i < NN) g_deg[i] = 0;
    if (i == 0) {
        int ok = 1;
        for (int e = 0; e < 64; e++) {
            long long v = p[e];
            if (v < 0 || v >= NN) { ok = 0; break; }
        }
        g_is64 = ok;
    }
}

__global__ void count_deg_kernel(const void* __restrict__ ei) {
    int e = blockIdx.x * blockDim.x + threadIdx.x;
    if (e >= NE) return;
    int d;
    if (g_is64) d = (int)((const long long*)ei)[NE + e];
    else        d = ((const int*)ei)[NE + e];
    atomicAdd(&g_deg[d], 1);
}

// single-block chunked exclusive scan, shuffle-based; dinv fused in
__global__ void scan_dinv_kernel() {
    __shared__ int warp_sums[32];
    int tid = threadIdx.x, lane = tid & 31, wid = tid >> 5;
    int carry = 0;
    for (int base = 0; base < NN; base += 1024) {
        int i = base + tid;
        int v = (i < NN) ? g_deg[i] : 0;
        if (i < NN) g_dinv[i] = rsqrtf((float)(v + 1));   // +1 self loop
        int s = v;
        #pragma unroll
        for (int o = 1; o < 32; o <<= 1) {
            int t = __shfl_up_sync(0xffffffffu, s, o);
            if (lane >= o) s += t;
        }
        if (lane == 31) warp_sums[wid] = s;
        __syncthreads();
        if (wid == 0) {
            int ws = warp_sums[lane];
            #pragma unroll
            for (int o = 1; o < 32; o <<= 1) {
                int t = __shfl_up_sync(0xffffffffu, ws, o);
                if (lane >= o) ws += t;
            }
            warp_sums[lane] = ws;
        }
        __syncthreads();
        int warp_excl = (wid == 0) ? 0 : warp_sums[wid - 1];
        int excl = carry + warp_excl + s - v;
        if (i < NN) { g_rowptr[i] = excl; g_cursor[i] = excl; }
        carry += warp_sums[31];
        __syncthreads();
    }
    if (tid == 0) g_rowptr[NN] = carry;
}

__global__ void scatter_kernel(const void* __restrict__ ei) {
    int e = blockIdx.x * blockDim.x + threadIdx.x;
    if (e >= NE) return;
    int s, d;
    if (g_is64) {
        s = (int)((const long long*)ei)[e];
        d = (int)((const long long*)ei)[NE + e];
    } else {
        s = ((const int*)ei)[e];
        d = ((const int*)ei)[NE + e];
    }
    int pos = atomicAdd(&g_cursor[d], 1);
    g_col[pos] = s;
}

// ---------------- bf16 split prep (x + both weights in one kernel) ----------
__device__ __forceinline__ void split_bf16(float v, __nv_bfloat16& hi,
                                           __nv_bfloat16& lo) {
    hi = __float2bfloat16(v);
    lo = __float2bfloat16(v - __bfloat162float(hi));
}

#define NX4   (NN * C_IN / 4)                     // 1,920,000 float4s of x
#define NW1   (C_HID * C_IN)
#define NW2   (C_OUT * C_HID)

__global__ void prep_kernel(const float* __restrict__ x,
                            const float* __restrict__ W1,
                            const float* __restrict__ W2) {
    int i = blockIdx.x * blockDim.x + threadIdx.x;
    if (i < NX4) {
        float4 v = ((const float4*)x)[i];
        __nv_bfloat16 h[4], l[4];
        split_bf16(v.x, h[0], l[0]); split_bf16(v.y, h[1], l[1]);
        split_bf16(v.z, h[2], l[2]); split_bf16(v.w, h[3], l[3]);
        *(uint2*)&g_xhi[(size_t)i * 4] = *(uint2*)h;
        *(uint2*)&g_xlo[(size_t)i * 4] = *(uint2*)l;
    } else {
        int j = i - NX4;
        if (j < NW1) {                         // W1^T[n][k] = W1[k][n]
            int n = j / C_IN, k = j % C_IN;
            split_bf16(W1[(size_t)k * C_HID + n], g_w1thi[j], g_w1tlo[j]);
        } else if (j < NW1 + NW2) {            // W2^T[n][k] = W2[k][n]
            int q = j - NW1;
            int n = q / C_HID, k = q % C_HID;
            split_bf16(W2[(size_t)k * C_OUT + n], g_w2thi[q], g_w2tlo[q]);
        }
    }
}

// ---------------- mma.sync helpers (baseline PTX — no sm_103a features) -----
__device__ __forceinline__ void ldm_x4(uint32_t& r0, uint32_t& r1,
                                       uint32_t& r2, uint32_t& r3,
                                       uint32_t addr) {
    asm volatile("ldmatrix.sync.aligned.m8n8.x4.shared.b16 {%0,%1,%2,%3}, [%4];"
                 : "=r"(r0), "=r"(r1), "=r"(r2), "=r"(r3) : "r"(addr));
}
__device__ __forceinline__ void mma_bf16(float* c, const uint32_t* a,
                                         const uint32_t* b) {
    asm volatile(
        "mma.sync.aligned.m16n8k16.row.col.f32.bf16.bf16.f32 "
        "{%0,%1,%2,%3}, {%4,%5,%6,%7}, {%8,%9}, {%0,%1,%2,%3};"
        : "+f"(c[0]), "+f"(c[1]), "+f"(c[2]), "+f"(c[3])
        : "r"(a[0]), "r"(a[1]), "r"(a[2]), "r"(a[3]), "r"(b[0]), "r"(b[1]));
}
__device__ __forceinline__ uint32_t smem_u32(const void* p) {
    uint32_t a;
    asm("{ .reg .u64 t; cvta.to.shared.u64 t, %1; cvt.u32.u64 %0, t; }"
        : "=r"(a) : "l"(p));
    return a;
}

// ---------------- tensor-core GEMM (HMMA) with fused dinv scale -------------
// out[row, n] = dinv[row] * sum_k A[row,k] * WT[n,k]
// 3-term bf16 split: AhiBhi + AloBhi + AhiBlo, fp32 accumulate.
// BM=128, BN = full N, BK=32, 256 threads = 8 warps (4 M x 2 N).
template<int BN, int K_TOT, int LAYER>
__global__ __launch_bounds__(256)
void gemm_mma_kernel() {
    constexpr int BM = 128, BK = 32;
    constexpr int STRIDE = BK + 8;              // bf16 units; 80B rows (conflict-free)
    constexpr int WN = BN / 2;                  // warp n-extent (64 / 32)
    constexpr int NFRAG = WN / 8;               // 8 / 4
    constexpr int MFRAG = 2;                    // 32 rows per warp

    const __nv_bfloat16 *Ahi, *Alo, *Bhi, *Blo;
    float* out;
    if constexpr (LAYER == 1) {
        Ahi = g_xhi;  Alo = g_xlo;  Bhi = g_w1thi; Blo = g_w1tlo; out = g_hs1;
    } else {
        Ahi = g_h2hi; Alo = g_h2lo; Bhi = g_w2thi; Blo = g_w2tlo; out = g_hs2;
    }

    __shared__ __nv_bfloat16 sAh[BM * STRIDE], sAl[BM * STRIDE];
    __shared__ __nv_bfloat16 sBh[BN * STRIDE], sBl[BN * STRIDE];

    const int tid   = threadIdx.x;
    const int wid   = tid >> 5, lane = tid & 31;
    const int warp_m = wid & 3, warp_n = wid >> 2;
    const int bRow  = blockIdx.x * BM;

    const uint32_t uAh = smem_u32(sAh), uAl = smem_u32(sAl);
    const uint32_t uBh = smem_u32(sBh), uBl = smem_u32(sBl);

    float acc[MFRAG][NFRAG][4];
    #pragma unroll
    for (int f = 0; f < MFRAG; f++)
        #pragma unroll
        for (int n = 0; n < NFRAG; n++)
            #pragma unroll
            for (int c = 0; c < 4; c++) acc[f][n][c] = 0.f;

    // ldmatrix per-lane row/col (same pattern for A[M][K] and B[N][K])
    const int lrow = lane & 15;
    const int lcol = (lane >> 4) << 3;

    for (int k0 = 0; k0 < K_TOT; k0 += BK) {
        // A slabs: BM x BK, vectorized uint4 (8 bf16)
        #pragma unroll
        for (int t = 0; t < BM * BK / 8 / 256; t++) {
            int u = t * 256 + tid;
            int r = u >> 2, c = u & 3;                  // 4 uint4 per row
            int grow = bRow + r;
            uint4 vh = make_uint4(0, 0, 0, 0), vl = make_uint4(0, 0, 0, 0);
            if (grow < NN) {
                size_t src = (size_t)grow * K_TOT + k0 + c * 8;
                vh = *(const uint4*)&Ahi[src];
                vl = *(const uint4*)&Alo[src];
            }
            *(uint4*)&sAh[r * STRIDE + c * 8] = vh;
            *(uint4*)&sAl[r * STRIDE + c * 8] = vl;
        }
        // B slabs: BN x BK
        #pragma unroll
        for (int t = 0; t < (BN * BK / 8 + 255) / 256; t++) {
            int u = t * 256 + tid;
            if (u < BN * BK / 8) {
                int r = u >> 2, c = u & 3;
                size_t src = (size_t)r * K_TOT + k0 + c * 8;
                *(uint4*)&sBh[r * STRIDE + c * 8] = *(const uint4*)&Bhi[src];
                *(uint4*)&sBl[r * STRIDE + c * 8] = *(const uint4*)&Blo[src];
            }
        }
        __syncthreads();

        #pragma unroll
        for (int kk = 0; kk < BK; kk += 16) {
            uint32_t ah[MFRAG][4], al[MFRAG][4];
            #pragma unroll
            for (int f = 0; f < MFRAG; f++) {
                uint32_t off = (uint32_t)((warp_m * 32 + f * 16 + lrow) * STRIDE
                                          + kk + lcol) * 2;
                ldm_x4(ah[f][0], ah[f][1], ah[f][2], ah[f][3], uAh + off);
                ldm_x4(al[f][0], al[f][1], al[f][2], al[f][3], uAl + off);
            }
            uint32_t bh[NFRAG][2], bl[NFRAG][2];
            #pragma unroll
            for (int g = 0; g < NFRAG / 2; g++) {
                uint32_t off = (uint32_t)((warp_n * WN + g * 16 + lrow) * STRIDE
                                          + kk + lcol) * 2;
                uint32_t r0, r1, r2, r3;
                ldm_x4(r0, r1, r2, r3, uBh + off);
                bh[2*g][0] = r0; bh[2*g][1] = r2;
                bh[2*g+1][0] = r1; bh[2*g+1][1] = r3;
                ldm_x4(r0, r1, r2, r3, uBl + off);
                bl[2*g][0] = r0; bl[2*g][1] = r2;
                bl[2*g+1][0] = r1; bl[2*g+1][1] = r3;
            }
            #pragma unroll
            for (int f = 0; f < MFRAG; f++)
                #pragma unroll
                for (int n = 0; n < NFRAG; n++) {
                    mma_bf16(acc[f][n], ah[f], bh[n]);   // hi*hi
                    mma_bf16(acc[f][n], al[f], bh[n]);   // lo*hi
                    mma_bf16(acc[f][n], ah[f], bl[n]);   // hi*lo
                }
        }
        __syncthreads();
    }

    // epilogue: D frag -> lane holds rows (q, q+8), cols 2*(lane%4)+{0,1}
    const int q  = lane >> 2;
    const int cc = (lane & 3) * 2;
    #pragma unroll
    for (int f = 0; f < MFRAG; f++) {
        int r0 = bRow + warp_m * 32 + f * 16 + q;
        int r1 = r0 + 8;
        float s0 = (r0 < NN) ? g_dinv[r0] : 0.f;
        float s1 = (r1 < NN) ? g_dinv[r1] : 0.f;
        #pragma unroll
        for (int n = 0; n < NFRAG; n++) {
            int col = warp_n * WN + n * 8 + cc;
            if (r0 < NN)
                *(float2*)&out[(size_t)r0 * BN + col] =
                    make_float2(acc[f][n][0] * s0, acc[f][n][1] * s0);
            if (r1 < NN)
                *(float2*)&out[(size_t)r1 * BN + col] =
                    make_float2(acc[f][n][2] * s1, acc[f][n][3] * s1);
        }
    }
}

// ---------------- CSR aggregation: one warp per node, MLP-4 unrolled --------
// layer 1: h2 = relu(dinv*(hs1[i] + sum_nbr) + b1), emitted as bf16 hi/lo split
__global__ void aggregate1_kernel(const float* __restrict__ bias) {
    int gw = (blockIdx.x * blockDim.x + threadIdx.x) >> 5;
    if (gw >= NN) return;
    int lane = threadIdx.x & 31;
    int off  = lane * 4;

    float acc[4];
    {
        float4 t = *(const float4*)&g_hs1[(size_t)gw * C_HID + off];
        acc[0] = t.x; acc[1] = t.y; acc[2] = t.z; acc[3] = t.w;
    }
    int s = g_rowptr[gw], e = g_rowptr[gw + 1];
    int i = s;
    for (; i + 4 <= e; i += 4) {               // MLP-4: batch cols, then rows
        int c0 = g_col[i], c1 = g_col[i + 1], c2 = g_col[i + 2], c3 = g_col[i + 3];
        float4 t0 = *(const float4*)&g_hs1[(size_t)c0 * C_HID + off];
        float4 t1 = *(const float4*)&g_hs1[(size_t)c1 * C_HID + off];
        float4 t2 = *(const float4*)&g_hs1[(size_t)c2 * C_HID + off];
        float4 t3 = *(const float4*)&g_hs1[(size_t)c3 * C_HID + off];
        acc[0] += (t0.x + t1.x) + (t2.x + t3.x);
        acc[1] += (t0.y + t1.y) + (t2.y + t3.y);
        acc[2] += (t0.z + t1.z) + (t2.z + t3.z);
        acc[3] += (t0.w + t1.w) + (t2.w + t3.w);
    }
    for (; i < e; i++) {
        float4 t = *(const float4*)&g_hs1[(size_t)g_col[i] * C_HID + off];
        acc[0] += t.x; acc[1] += t.y; acc[2] += t.z; acc[3] += t.w;
    }
    float di = g_dinv[gw];
    __nv_bfloat16 h[4], l[4];
    #pragma unroll
    for (int v = 0; v < 4; v++) {
        float val = fmaxf(fmaf(acc[v], di, bias[off + v]), 0.f);
        split_bf16(val, h[v], l[v]);
    }
    size_t idx = (size_t)gw * C_HID + off;
    *(uint2*)&g_h2hi[idx] = *(uint2*)h;
    *(uint2*)&g_h2lo[idx] = *(uint2*)l;
}

// layer 2: out = dinv*(hs2[i] + sum_nbr) + b2   (fp32 to d_out)
__global__ void aggregate2_kernel(const float* __restrict__ bias,
                                  float* __restrict__ out) {
    int gw = (blockIdx.x * blockDim.x + threadIdx.x) >> 5;
    if (gw >= NN) return;
    int lane = threadIdx.x & 31;
    int off  = lane * 2;

    float acc[2];
    {
        float2 t = *(const float2*)&g_hs2[(size_t)gw * C_OUT + off];
        acc[0] = t.x; acc[1] = t.y;
    }
    int s = g_rowptr[gw], e = g_rowptr[gw + 1];
    int i = s;
    for (; i + 4 <= e; i += 4) {
        int c0 = g_col[i], c1 = g_col[i + 1], c2 = g_col[i + 2], c3 = g_col[i + 3];
        float2 t0 = *(const float2*)&g_hs2[(size_t)c0 * C_OUT + off];
        float2 t1 = *(const float2*)&g_hs2[(size_t)c1 * C_OUT + off];
        float2 t2 = *(const float2*)&g_hs2[(size_t)c2 * C_OUT + off];
        float2 t3 = *(const float2*)&g_hs2[(size_t)c3 * C_OUT + off];
        acc[0] += (t0.x + t1.x) + (t2.x + t3.x);
        acc[1] += (t0.y + t1.y) + (t2.y + t3.y);
    }
    for (; i < e; i++) {
        float2 t = *(const float2*)&g_hs2[(size_t)g_col[i] * C_OUT + off];
        acc[0] += t.x; acc[1] += t.y;
    }
    float di = g_dinv[gw];
    float2 r = make_float2(fmaf(acc[0], di, bias[off]),
                           fmaf(acc[1], di, bias[off + 1]));
    *(float2*)&out[(size_t)gw * C_OUT + off] = r;
}

// ---------------- launch ------------------------------------------------------
extern "C" void kernel_launch(void* const* d_in, const int* in_sizes, int n_in,
                              void* d_out, int out_size) {
    const float* x  = (const float*)d_in[0];
    const void*  ei = d_in[1];                 // int64 (or int32) [2, E]
    const float* W1 = (const float*)d_in[2];
    const float* b1 = (const float*)d_in[3];
    const float* W2 = (const float*)d_in[4];
    const float* b2 = (const float*)d_in[5];
    float* out = (float*)d_out;

    // operand prep (bf16 splits) — independent of CSR, launched first
    prep_kernel<<<(NX4 + NW1 + NW2 + 255) / 256, 256>>>(x, W1, W2);

    // CSR build
    init_kernel<<<(NN + 255) / 256, 256>>>((const long long*)ei);
    count_deg_kernel<<<(NE + 255) / 256, 256>>>(ei);
    scan_dinv_kernel<<<1, 1024>>>();
    scatter_kernel<<<(NE + 255) / 256, 256>>>(ei);

    constexpr int GB = (NN + 127) / 128;  // 235 CTAs
    // layer 1
    gemm_mma_kernel<C_HID, C_IN, 1><<<GB, 256>>>();
    aggregate1_kernel<<<(NN * 32 + 255) / 256, 256>>>(b1);
    // layer 2
    gemm_mma_kernel<C_OUT, C_HID, 2><<<GB, 256>>>();
    aggregate2_kernel<<<(NN * 32 + 255) / 256, 256>>>(b2, out);
}

// round 13
// speedup vs baseline: 1.5180x; 1.0002x over previous
#include <cuda_runtime.h>
#include <cuda_bf16.h>
#include <cstdint>

#define NN    30000
#define NE    600000
#define C_IN  256
#define C_HID 128
#define C_OUT 64

// ---------------- scratch (device globals — no allocation allowed) ----------
__device__ int   g_deg[NN];
__device__ float g_dinv[NN];
__device__ int   g_rowptr[NN + 1];
__device__ int   g_cursor[NN];
__device__ int   g_col[NE];
__device__ int   g_is64;
__device__ float g_hs1[(size_t)NN * C_HID];   // dinv * (X @ W1)
__device__ float g_hs2[(size_t)NN * C_OUT];   // dinv * (h2 @ W2)
// bf16 split operands for tensor-core GEMMs
__device__ __nv_bfloat16 g_xhi [(size_t)NN * C_IN];
__device__ __nv_bfloat16 g_xlo [(size_t)NN * C_IN];
__device__ __nv_bfloat16 g_h2hi[(size_t)NN * C_HID];
__device__ __nv_bfloat16 g_h2lo[(size_t)NN * C_HID];
__device__ __nv_bfloat16 g_w1thi[C_HID * C_IN];   // W1^T [n][k]
__device__ __nv_bfloat16 g_w1tlo[C_HID * C_IN];
__device__ __nv_bfloat16 g_w2thi[C_OUT * C_HID];  // W2^T [n][k]
__device__ __nv_bfloat16 g_w2tlo[C_OUT * C_HID];

// ---------------- init: zero degrees + edge dtype detection (fused) ---------
__global__ void init_kernel(const long long* __restrict__ p) {
    int i = blockIdx.x * blockDim.x + threadIdx.x;
    if (i < NN) g_deg[i] = 0;
    if (i == 0) {
        int ok = 1;
        for (int e = 0; e < 64; e++) {
            long long v = p[e];
            if (v < 0 || v >= NN) { ok = 0; break; }
        }
        g_is64 = ok;
    }
}

__global__ void count_deg_kernel(const void* __restrict__ ei) {
    int e = blockIdx.x * blockDim.x + threadIdx.x;
    if (e >= NE) return;
    int d;
    if (g_is64) d = (int)((const long long*)ei)[NE + e];
    else        d = ((const int*)ei)[NE + e];
    atomicAdd(&g_deg[d], 1);
}

// single-block chunked exclusive scan, shuffle-based; dinv fused in
__global__ void scan_dinv_kernel() {
    __shared__ int warp_sums[32];
    int tid = threadIdx.x, lane = tid & 31, wid = tid >> 5;
    int carry = 0;
    for (int base = 0; base < NN; base += 1024) {
        int i = base + tid;
        int v = (i < NN) ? g_deg[i] : 0;
        if (i < NN) g_dinv[i] = rsqrtf((float)(v + 1));   // +1 self loop
        int s = v;
        #pragma unroll
        for (int o = 1; o < 32; o <<= 1) {
            int t = __shfl_up_sync(0xffffffffu, s, o);
            if (lane >= o) s += t;
        }
        if (lane == 31) warp_sums[wid] = s;
        __syncthreads();
        if (wid == 0) {
            int ws = warp_sums[lane];
            #pragma unroll
            for (int o = 1; o < 32; o <<= 1) {
                int t = __shfl_up_sync(0xffffffffu, ws, o);
                if (lane >= o) ws += t;
            }
            warp_sums[lane] = ws;
        }
        __syncthreads();
        int warp_excl = (wid == 0) ? 0 : warp_sums[wid - 1];
        int excl = carry + warp_excl + s - v;
        if (i < NN) { g_rowptr[i] = excl; g_cursor[i] = excl; }
        carry += warp_sums[31];
        __syncthreads();
    }
    if (tid == 0) g_rowptr[NN] = carry;
}

__global__ void scatter_kernel(const void* __restrict__ ei) {
    int e = blockIdx.x * blockDim.x + threadIdx.x;
    if (e >= NE) return;
    int s, d;
    if (g_is64) {
        s = (int)((const long long*)ei)[e];
        d = (int)((const long long*)ei)[NE + e];
    } else {
        s = ((const int*)ei)[e];
        d = ((const int*)ei)[NE + e];
    }
    int pos = atomicAdd(&g_cursor[d], 1);
    g_col[pos] = s;
}

// ---------------- bf16 split prep (x + both weights in one kernel) ----------
__device__ __forceinline__ void split_bf16(float v, __nv_bfloat16& hi,
                                           __nv_bfloat16& lo) {
    hi = __float2bfloat16(v);
    lo = __float2bfloat16(v - __bfloat162float(hi));
}

#define NX4   (NN * C_IN / 4)                     // 1,920,000 float4s of x
#define NW1   (C_HID * C_IN)
#define NW2   (C_OUT * C_HID)

__global__ void prep_kernel(const float* __restrict__ x,
                            const float* __restrict__ W1,
                            const float* __restrict__ W2) {
    int i = blockIdx.x * blockDim.x + threadIdx.x;
    if (i < NX4) {
        float4 v = ((const float4*)x)[i];
        __nv_bfloat16 h[4], l[4];
        split_bf16(v.x, h[0], l[0]); split_bf16(v.y, h[1], l[1]);
        split_bf16(v.z, h[2], l[2]); split_bf16(v.w, h[3], l[3]);
        *(uint2*)&g_xhi[(size_t)i * 4] = *(uint2*)h;
        *(uint2*)&g_xlo[(size_t)i * 4] = *(uint2*)l;
    } else {
        int j = i - NX4;
        if (j < NW1) {                         // W1^T[n][k] = W1[k][n]
            int n = j / C_IN, k = j % C_IN;
            split_bf16(W1[(size_t)k * C_HID + n], g_w1thi[j], g_w1tlo[j]);
        } else if (j < NW1 + NW2) {            // W2^T[n][k] = W2[k][n]
            int q = j - NW1;
            int n = q / C_HID, k = q % C_HID;
            split_bf16(W2[(size_t)k * C_OUT + n], g_w2thi[q], g_w2tlo[q]);
        }
    }
}

// ---------------- mma.sync helpers (baseline PTX — no sm_103a features) -----
__device__ __forceinline__ void ldm_x4(uint32_t& r0, uint32_t& r1,
                                       uint32_t& r2, uint32_t& r3,
                                       uint32_t addr) {
    asm volatile("ldmatrix.sync.aligned.m8n8.x4.shared.b16 {%0,%1,%2,%3}, [%4];"
                 : "=r"(r0), "=r"(r1), "=r"(r2), "=r"(r3) : "r"(addr));
}
__device__ __forceinline__ void mma_bf16(float* c, const uint32_t* a,
                                         const uint32_t* b) {
    asm volatile(
        "mma.sync.aligned.m16n8k16.row.col.f32.bf16.bf16.f32 "
        "{%0,%1,%2,%3}, {%4,%5,%6,%7}, {%8,%9}, {%0,%1,%2,%3};"
        : "+f"(c[0]), "+f"(c[1]), "+f"(c[2]), "+f"(c[3])
        : "r"(a[0]), "r"(a[1]), "r"(a[2]), "r"(a[3]), "r"(b[0]), "r"(b[1]));
}
__device__ __forceinline__ uint32_t smem_u32(const void* p) {
    uint32_t a;
    asm("{ .reg .u64 t; cvta.to.shared.u64 t, %1; cvt.u32.u64 %0, t; }"
        : "=r"(a) : "l"(p));
    return a;
}

// ---------------- tensor-core GEMM (HMMA) with fused dinv scale -------------
// out[row, n] = dinv[row] * sum_k A[row,k] * WT[n,k]
// 3-term bf16 split: AhiBhi + AloBhi + AhiBlo, fp32 accumulate.
// BM=128, BN = full N, BK=32, 256 threads = 8 warps (4 M x 2 N).
template<int BN, int K_TOT, int LAYER>
__global__ __launch_bounds__(256)
void gemm_mma_kernel() {
    constexpr int BM = 128, BK = 32;
    constexpr int STRIDE = BK + 8;              // bf16 units; 80B rows (conflict-free)
    constexpr int WN = BN / 2;                  // warp n-extent (64 / 32)
    constexpr int NFRAG = WN / 8;               // 8 / 4
    constexpr int MFRAG = 2;                    // 32 rows per warp

    const __nv_bfloat16 *Ahi, *Alo, *Bhi, *Blo;
    float* out;
    if constexpr (LAYER == 1) {
        Ahi = g_xhi;  Alo = g_xlo;  Bhi = g_w1thi; Blo = g_w1tlo; out = g_hs1;
    } else {
        Ahi = g_h2hi; Alo = g_h2lo; Bhi = g_w2thi; Blo = g_w2tlo; out = g_hs2;
    }

    __shared__ __nv_bfloat16 sAh[BM * STRIDE], sAl[BM * STRIDE];
    __shared__ __nv_bfloat16 sBh[BN * STRIDE], sBl[BN * STRIDE];

    const int tid   = threadIdx.x;
    const int wid   = tid >> 5, lane = tid & 31;
    const int warp_m = wid & 3, warp_n = wid >> 2;
    const int bRow  = blockIdx.x * BM;

    const uint32_t uAh = smem_u32(sAh), uAl = smem_u32(sAl);
    const uint32_t uBh = smem_u32(sBh), uBl = smem_u32(sBl);

    float acc[MFRAG][NFRAG][4];
    #pragma unroll
    for (int f = 0; f < MFRAG; f++)
        #pragma unroll
        for (int n = 0; n < NFRAG; n++)
            #pragma unroll
            for (int c = 0; c < 4; c++) acc[f][n][c] = 0.f;

    // ldmatrix per-lane row/col (same pattern for A[M][K] and B[N][K])
    const int lrow = lane & 15;
    const int lcol = (lane >> 4) << 3;

    for (int k0 = 0; k0 < K_TOT; k0 += BK) {
        // A slabs: BM x BK, vectorized uint4 (8 bf16)
        #pragma unroll
        for (int t = 0; t < BM * BK / 8 / 256; t++) {
            int u = t * 256 + tid;
            int r = u >> 2, c = u & 3;                  // 4 uint4 per row
            int grow = bRow + r;
            uint4 vh = make_uint4(0, 0, 0, 0), vl = make_uint4(0, 0, 0, 0);
            if (grow < NN) {
                size_t src = (size_t)grow * K_TOT + k0 + c * 8;
                vh = *(const uint4*)&Ahi[src];
                vl = *(const uint4*)&Alo[src];
            }
            *(uint4*)&sAh[r * STRIDE + c * 8] = vh;
            *(uint4*)&sAl[r * STRIDE + c * 8] = vl;
        }
        // B slabs: BN x BK
        #pragma unroll
        for (int t = 0; t < (BN * BK / 8 + 255) / 256; t++) {
            int u = t * 256 + tid;
            if (u < BN * BK / 8) {
                int r = u >> 2, c = u & 3;
                size_t src = (size_t)r * K_TOT + k0 + c * 8;
                *(uint4*)&sBh[r * STRIDE + c * 8] = *(const uint4*)&Bhi[src];
                *(uint4*)&sBl[r * STRIDE + c * 8] = *(const uint4*)&Blo[src];
            }
        }
        __syncthreads();

        #pragma unroll
        for (int kk = 0; kk < BK; kk += 16) {
            uint32_t ah[MFRAG][4], al[MFRAG][4];
            #pragma unroll
            for (int f = 0; f < MFRAG; f++) {
                uint32_t off = (uint32_t)((warp_m * 32 + f * 16 + lrow) * STRIDE
                                          + kk + lcol) * 2;
                ldm_x4(ah[f][0], ah[f][1], ah[f][2], ah[f][3], uAh + off);
                ldm_x4(al[f][0], al[f][1], al[f][2], al[f][3], uAl + off);
            }
            uint32_t bh[NFRAG][2], bl[NFRAG][2];
            #pragma unroll
            for (int g = 0; g < NFRAG / 2; g++) {
                uint32_t off = (uint32_t)((warp_n * WN + g * 16 + lrow) * STRIDE
                                          + kk + lcol) * 2;
                uint32_t r0, r1, r2, r3;
                ldm_x4(r0, r1, r2, r3, uBh + off);
                bh[2*g][0] = r0; bh[2*g][1] = r2;
                bh[2*g+1][0] = r1; bh[2*g+1][1] = r3;
                ldm_x4(r0, r1, r2, r3, uBl + off);
                bl[2*g][0] = r0; bl[2*g][1] = r2;
                bl[2*g+1][0] = r1; bl[2*g+1][1] = r3;
            }
            #pragma unroll
            for (int f = 0; f < MFRAG; f++)
                #pragma unroll
                for (int n = 0; n < NFRAG; n++) {
                    mma_bf16(acc[f][n], ah[f], bh[n]);   // hi*hi
                    mma_bf16(acc[f][n], al[f], bh[n]);   // lo*hi
                    mma_bf16(acc[f][n], ah[f], bl[n]);   // hi*lo
                }
        }
        __syncthreads();
    }

    // epilogue: D frag -> lane holds rows (q, q+8), cols 2*(lane%4)+{0,1}
    const int q  = lane >> 2;
    const int cc = (lane & 3) * 2;
    #pragma unroll
    for (int f = 0; f < MFRAG; f++) {
        int r0 = bRow + warp_m * 32 + f * 16 + q;
        int r1 = r0 + 8;
        float s0 = (r0 < NN) ? g_dinv[r0] : 0.f;
        float s1 = (r1 < NN) ? g_dinv[r1] : 0.f;
        #pragma unroll
        for (int n = 0; n < NFRAG; n++) {
            int col = warp_n * WN + n * 8 + cc;
            if (r0 < NN)
                *(float2*)&out[(size_t)r0 * BN + col] =
                    make_float2(acc[f][n][0] * s0, acc[f][n][1] * s0);
            if (r1 < NN)
                *(float2*)&out[(size_t)r1 * BN + col] =
                    make_float2(acc[f][n][2] * s1, acc[f][n][3] * s1);
        }
    }
}

// ---------------- CSR aggregation: one warp per node, MLP-4 unrolled --------
// layer 1: h2 = relu(dinv*(hs1[i] + sum_nbr) + b1), emitted as bf16 hi/lo split
__global__ void aggregate1_kernel(const float* __restrict__ bias) {
    int gw = (blockIdx.x * blockDim.x + threadIdx.x) >> 5;
    if (gw >= NN) return;
    int lane = threadIdx.x & 31;
    int off  = lane * 4;

    float acc[4];
    {
        float4 t = *(const float4*)&g_hs1[(size_t)gw * C_HID + off];
        acc[0] = t.x; acc[1] = t.y; acc[2] = t.z; acc[3] = t.w;
    }
    int s = g_rowptr[gw], e = g_rowptr[gw + 1];
    int i = s;
    for (; i + 4 <= e; i += 4) {               // MLP-4: batch cols, then rows
        int c0 = g_col[i], c1 = g_col[i + 1], c2 = g_col[i + 2], c3 = g_col[i + 3];
        float4 t0 = *(const float4*)&g_hs1[(size_t)c0 * C_HID + off];
        float4 t1 = *(const float4*)&g_hs1[(size_t)c1 * C_HID + off];
        float4 t2 = *(const float4*)&g_hs1[(size_t)c2 * C_HID + off];
        float4 t3 = *(const float4*)&g_hs1[(size_t)c3 * C_HID + off];
        acc[0] += (t0.x + t1.x) + (t2.x + t3.x);
        acc[1] += (t0.y + t1.y) + (t2.y + t3.y);
        acc[2] += (t0.z + t1.z) + (t2.z + t3.z);
        acc[3] += (t0.w + t1.w) + (t2.w + t3.w);
    }
    for (; i < e; i++) {
        float4 t = *(const float4*)&g_hs1[(size_t)g_col[i] * C_HID + off];
        acc[0] += t.x; acc[1] += t.y; acc[2] += t.z; acc[3] += t.w;
    }
    float di = g_dinv[gw];
    __nv_bfloat16 h[4], l[4];
    #pragma unroll
    for (int v = 0; v < 4; v++) {
        float val = fmaxf(fmaf(acc[v], di, bias[off + v]), 0.f);
        split_bf16(val, h[v], l[v]);
    }
    size_t idx = (size_t)gw * C_HID + off;
    *(uint2*)&g_h2hi[idx] = *(uint2*)h;
    *(uint2*)&g_h2lo[idx] = *(uint2*)l;
}

// layer 2: out = dinv*(hs2[i] + sum_nbr) + b2   (fp32 to d_out)
__global__ void aggregate2_kernel(const float* __restrict__ bias,
                                  float* __restrict__ out) {
    int gw = (blockIdx.x * blockDim.x + threadIdx.x) >> 5;
    if (gw >= NN) return;
    int lane = threadIdx.x & 31;
    int off  = lane * 2;

    float acc[2];
    {
        float2 t = *(const float2*)&g_hs2[(size_t)gw * C_OUT + off];
        acc[0] = t.x; acc[1] = t.y;
    }
    int s = g_rowptr[gw], e = g_rowptr[gw + 1];
    int i = s;
    for (; i + 4 <= e; i += 4) {
        int c0 = g_col[i], c1 = g_col[i + 1], c2 = g_col[i + 2], c3 = g_col[i + 3];
        float2 t0 = *(const float2*)&g_hs2[(size_t)c0 * C_OUT + off];
        float2 t1 = *(const float2*)&g_hs2[(size_t)c1 * C_OUT + off];
        float2 t2 = *(const float2*)&g_hs2[(size_t)c2 * C_OUT + off];
        float2 t3 = *(const float2*)&g_hs2[(size_t)c3 * C_OUT + off];
        acc[0] += (t0.x + t1.x) + (t2.x + t3.x);
        acc[1] += (t0.y + t1.y) + (t2.y + t3.y);
    }
    for (; i < e; i++) {
        float2 t = *(const float2*)&g_hs2[(size_t)g_col[i] * C_OUT + off];
        acc[0] += t.x; acc[1] += t.y;
    }
    float di = g_dinv[gw];
    float2 r = make_float2(fmaf(acc[0], di, bias[off]),
                           fmaf(acc[1], di, bias[off + 1]));
    *(float2*)&out[(size_t)gw * C_OUT + off] = r;
}

// ---------------- launch ------------------------------------------------------
extern "C" void kernel_launch(void* const* d_in, const int* in_sizes, int n_in,
                              void* d_out, int out_size) {
    const float* x  = (const float*)d_in[0];
    const void*  ei = d_in[1];                 // int64 (or int32) [2, E]
    const float* W1 = (const float*)d_in[2];
    const float* b1 = (const float*)d_in[3];
    const float* W2 = (const float*)d_in[4];
    const float* b2 = (const float*)d_in[5];
    float* out = (float*)d_out;

    // operand prep (bf16 splits) — independent of CSR, launched first
    prep_kernel<<<(NX4 + NW1 + NW2 + 255) / 256, 256>>>(x, W1, W2);

    // CSR build
    init_kernel<<<(NN + 255) / 256, 256>>>((const long long*)ei);
    count_deg_kernel<<<(NE + 255) / 256, 256>>>(ei);
    scan_dinv_kernel<<<1, 1024>>>();
    scatter_kernel<<<(NE + 255) / 256, 256>>>(ei);

    constexpr int GB = (NN + 127) / 128;  // 235 CTAs
    // layer 1
    gemm_mma_kernel<C_HID, C_IN, 1><<<GB, 256>>>();
    aggregate1_kernel<<<(NN * 32 + 255) / 256, 256>>>(b1);
    // layer 2
    gemm_mma_kernel<C_OUT, C_HID, 2><<<GB, 256>>>();
    aggregate2_kernel<<<(NN * 32 + 255) / 256, 256>>>(b2, out);
}